// round 1
// baseline (speedup 1.0000x reference)
#include <cuda_runtime.h>
#include <cstdint>

#define B    8
#define S    1024
#define D    96
#define G    8
#define MTOT (D*D)          // 9216
#define LN_EPS 1e-5f
#define TWO_PI 6.283185307179586f

// ---------------- scratch (device globals; no allocation allowed) ----------
__device__ float g_Z0[B*S*D];     // pre-LN projection            (3 MB)
__device__ float g_Z [B*S*D];     // layer-normed                 (3 MB)
__device__ float g_W [S*MTOT];    // W[s, i*96+j]                 (36 MB)
__device__ float g_A [S*B*D];     // (T+Z0) as A[s, b*96+i]       (3 MB)

// ---------------- K1: Z0 = x @ M^T ; Z = LN(Z0) ----------------------------
// one block per (b,s) row, 96 threads (3 full warps)
__global__ void k1_proj_ln(const float* __restrict__ x,
                           const float* __restrict__ M,
                           const float* __restrict__ gamma,
                           const float* __restrict__ beta)
{
    const int row = blockIdx.x;      // b*S + s
    const int i   = threadIdx.x;     // 0..95
    __shared__ float sx[D];
    __shared__ float sSum[3], sSq[3];

    sx[i] = x[(size_t)row*D + i];
    __syncthreads();

    // dot(M[i,:], x_row) with float4
    float acc = 0.f;
    const float4* M4 = reinterpret_cast<const float4*>(M + (size_t)i*D);
    const float4* X4 = reinterpret_cast<const float4*>(sx);
#pragma unroll
    for (int j4 = 0; j4 < D/4; ++j4) {
        float4 m = M4[j4];
        float4 v = X4[j4];
        acc = fmaf(m.x, v.x, acc);
        acc = fmaf(m.y, v.y, acc);
        acc = fmaf(m.z, v.z, acc);
        acc = fmaf(m.w, v.w, acc);
    }
    g_Z0[(size_t)row*D + i] = acc;

    // block reduce mean / mean-of-squares over 96 lanes
    float s1 = acc, s2 = acc*acc;
#pragma unroll
    for (int o = 16; o; o >>= 1) {
        s1 += __shfl_xor_sync(0xffffffffu, s1, o);
        s2 += __shfl_xor_sync(0xffffffffu, s2, o);
    }
    const int wid = i >> 5, lane = i & 31;
    if (lane == 0) { sSum[wid] = s1; sSq[wid] = s2; }
    __syncthreads();
    const float mu  = (sSum[0]+sSum[1]+sSum[2]) * (1.f/D);
    const float ex2 = (sSq[0]+sSq[1]+sSq[2]) * (1.f/D);
    const float var = ex2 - mu*mu;
    const float rstd = rsqrtf(var + LN_EPS);
    g_Z[(size_t)row*D + i] = (acc - mu)*rstd*gamma[i] + beta[i];
}

// ---------------- K2: W[s,m] = sum_g P[m*8+g] * cos(2*pi*s/(8m+g+2)) -------
// Chebyshev recurrence over s; each thread owns one m and a 128-long s chunk.
// Seeds use integer s mod p so cosf sees an argument in [0, 2*pi).
#define SCHUNK 128
__global__ void k2_basis(const float* __restrict__ P)
{
    const int gidx  = blockIdx.x*blockDim.x + threadIdx.x; // 0..73727
    const int m     = gidx % MTOT;
    const int chunk = gidx / MTOT;
    const int s0    = chunk * SCHUNK;

    float kg[G], c0[G], c1[G], Pv[G];
#pragma unroll
    for (int g = 0; g < G; ++g) {
        const int p   = m*G + g + 2;
        const float fp = (float)p;
        kg[g] = 2.f * cosf(TWO_PI / fp);
        const int r0  = s0 % p;
        const int rm1 = (s0 + p - 1) % p;       // (s0-1) mod p, cos is even+periodic
        c1[g] = cosf(TWO_PI * (float)r0  / fp); // cos(s0 * w)
        c0[g] = cosf(TWO_PI * (float)rm1 / fp); // cos((s0-1) * w)
        Pv[g] = P[m*G + g];
    }

    float* Wp = g_W + (size_t)s0*MTOT + m;
    for (int s = 0; s < SCHUNK; ++s) {
        float w = 0.f;
#pragma unroll
        for (int g = 0; g < G; ++g) w = fmaf(Pv[g], c1[g], w);
        Wp[(size_t)s*MTOT] = w;
#pragma unroll
        for (int g = 0; g < G; ++g) {
            const float cn = fmaf(kg[g], c1[g], -c0[g]);
            c0[g] = c1[g];
            c1[g] = cn;
        }
    }
}

// ---------------- K3: A[s, b*96+i] = Z0[b,s,i] + sum_j Z[b,s,j]*W[s,i,j] ---
// one block per s; W[s] transposed into padded smem (stride 97: no conflicts)
__global__ __launch_bounds__(768) void k3_apply(void)
{
    const int s   = blockIdx.x;
    const int tid = threadIdx.x;     // 0..767
    __shared__ float sWt[D*97];      // sWt[j*97 + i] = W[s, i*96+j]
    __shared__ float sZ[B*D];

    const float* Ws = g_W + (size_t)s*MTOT;
#pragma unroll
    for (int r = 0; r < 12; ++r) {
        const int f = tid + r*768;           // flat i*96+j
        const int i = f / D, j = f % D;
        sWt[j*97 + i] = Ws[f];
    }
    {
        const int b = tid / D, i = tid % D;
        sZ[tid] = g_Z[((size_t)b*S + s)*D + i];
    }
    __syncthreads();

    const int b = tid / D, i = tid % D;
    const float* zrow = sZ + b*D;
    float acc = 0.f;
#pragma unroll 8
    for (int j = 0; j < D; ++j)
        acc = fmaf(zrow[j], sWt[j*97 + i], acc);

    g_A[(size_t)s*(B*D) + tid] = acc + g_Z0[((size_t)b*S + s)*D + i];
}

// ---------------- K4: out[b,t,i] = sum_s L[s,t] * A[s, b*96+i] -------------
// single fused GEMM for U + residual: M=1024(t), N=768(n=b*96+i), K=1024(s)
#define BT 64
#define BN 64
#define BK 16
__global__ __launch_bounds__(256) void k4_gemm(const float* __restrict__ L,
                                               float* __restrict__ out)
{
    __shared__ float Ls[BK][BT];
    __shared__ float As[BK][BN];
    const int tid = threadIdx.x;
    const int n0  = blockIdx.x * BN;
    const int t0  = blockIdx.y * BT;
    const int tx  = tid & 15;        // n micro
    const int ty  = tid >> 4;        // t micro
    float acc[4][4] = {};

    for (int ks = 0; ks < S; ks += BK) {
#pragma unroll
        for (int r = 0; r < 4; ++r) {
            const int f  = tid + r*256;
            const int kk = f >> 6, c = f & 63;
            Ls[kk][c] = L  [(size_t)(ks+kk)*S      + t0 + c];
            As[kk][c] = g_A[(size_t)(ks+kk)*(B*D)  + n0 + c];
        }
        __syncthreads();
#pragma unroll
        for (int kk = 0; kk < BK; ++kk) {
            const float4 lv = *reinterpret_cast<const float4*>(&Ls[kk][ty*4]);
            const float4 av = *reinterpret_cast<const float4*>(&As[kk][tx*4]);
            const float l[4] = {lv.x, lv.y, lv.z, lv.w};
            const float a[4] = {av.x, av.y, av.z, av.w};
#pragma unroll
            for (int u = 0; u < 4; ++u)
#pragma unroll
                for (int v = 0; v < 4; ++v)
                    acc[u][v] = fmaf(l[u], a[v], acc[u][v]);
        }
        __syncthreads();
    }

#pragma unroll
    for (int u = 0; u < 4; ++u) {
        const int t = t0 + ty*4 + u;
#pragma unroll
        for (int v = 0; v < 4; ++v) {
            const int n = n0 + tx*4 + v;
            const int b = n / D, i = n % D;
            out[(size_t)b*(S*D) + (size_t)t*D + i] = acc[u][v];
        }
    }
}

// ---------------- launch ----------------------------------------------------
extern "C" void kernel_launch(void* const* d_in, const int* in_sizes, int n_in,
                              void* d_out, int out_size)
{
    const float* x     = (const float*)d_in[0];   // (8,1024,96)
    const float* M     = (const float*)d_in[1];   // (96,96)
    const float* P     = (const float*)d_in[2];   // (96,96,8)
    const float* L     = (const float*)d_in[3];   // (1024,1024)
    const float* gamma = (const float*)d_in[4];   // (96)
    const float* beta  = (const float*)d_in[5];   // (96)
    float* out = (float*)d_out;                   // (8,1024,96)

    k1_proj_ln<<<B*S, D>>>(x, M, gamma, beta);
    k2_basis  <<<(MTOT*(S/SCHUNK))/256, 256>>>(P);   // 288 blocks x 256
    k3_apply  <<<S, 768>>>();
    k4_gemm   <<<dim3((B*D)/BN, S/BT), 256>>>(L, out);
}

// round 2
// speedup vs baseline: 1.6612x; 1.6612x over previous
#include <cuda_runtime.h>
#include <cstdint>

#define B    8
#define S    1024
#define D    96
#define G    8
#define MTOT (D*D)          // 9216
#define ND   (B*D)          // 768
#define LN_EPS 1e-5f
#define TWO_PI 6.283185307179586f

// ---------------- scratch (device globals; no allocation allowed) ----------
__device__ float g_W   [S*MTOT];       // W[s, i*96+j]                 (36 MB)
__device__ float g_A   [S*ND];         // (T+Z0) as A[s, b*96+i]       (3 MB)
__device__ float g_part[4*S*ND];       // split-K partials             (12.6 MB)

// ---------------- K2: W[s,m] = sum_g P[m*8+g] * cos(2*pi*s/(8m+g+2)) -------
// Chebyshev recurrence over s; thread owns one m and a 64-long s chunk.
#define SCHUNK 64
__global__ void k2_basis(const float* __restrict__ P)
{
    const int gidx  = blockIdx.x*blockDim.x + threadIdx.x;
    const int m     = gidx % MTOT;
    const int chunk = gidx / MTOT;
    const int s0    = chunk * SCHUNK;

    float kg[G], c0[G], c1[G], Pv[G];
#pragma unroll
    for (int g = 0; g < G; ++g) {
        const int p    = m*G + g + 2;
        const float fp = (float)p;
        kg[g] = 2.f * cosf(TWO_PI / fp);
        const int r0  = s0 % p;
        const int rm1 = (s0 + p - 1) % p;        // (s0-1) mod p
        c1[g] = cosf(TWO_PI * (float)r0  / fp);  // cos(s0*w)
        c0[g] = cosf(TWO_PI * (float)rm1 / fp);  // cos((s0-1)*w)
        Pv[g] = P[m*G + g];
    }

    float* Wp = g_W + (size_t)s0*MTOT + m;
    for (int s = 0; s < SCHUNK; ++s) {
        float w = 0.f;
#pragma unroll
        for (int g = 0; g < G; ++g) w = fmaf(Pv[g], c1[g], w);
        Wp[(size_t)s*MTOT] = w;
#pragma unroll
        for (int g = 0; g < G; ++g) {
            const float cn = fmaf(kg[g], c1[g], -c0[g]);
            c0[g] = c1[g];
            c1[g] = cn;
        }
    }
}

// ---------------- K13: fused project + LN + per-s mixing + residual --------
// one block per s, 768 threads = (b,i). smem buffer reused: M^T then W^T.
__global__ __launch_bounds__(768) void k13_fused(const float* __restrict__ x,
                                                 const float* __restrict__ M,
                                                 const float* __restrict__ gamma,
                                                 const float* __restrict__ beta)
{
    const int s   = blockIdx.x;
    const int tid = threadIdx.x;       // b*96 + i
    const int b   = tid / D;
    const int i   = tid % D;

    __shared__ float sT [D*97];        // phase1: M^T[j*97+i]; phase2: W^T[j*97+i]
    __shared__ float sx [ND];          // x[b*96+j]
    __shared__ float sZ [ND];          // LN'd Z[b*96+j]
    __shared__ float sR [24][2];       // warp partial sums

    // prefetch this block's W row-chunk into registers (flies during phase 1)
    float wreg[12];
    const float* Ws = g_W + (size_t)s*MTOT;
#pragma unroll
    for (int r = 0; r < 12; ++r) wreg[r] = Ws[tid + r*768];

    // stage x rows for all b at this s
    sx[tid] = x[((size_t)b*S + s)*D + i];

    // stage M transposed: sT[j*97+i] = M[i*96+j]
#pragma unroll
    for (int r = 0; r < 12; ++r) {
        const int f = tid + r*768;            // f = i'*96 + j'
        sT[(f % D)*97 + f / D] = M[f];
    }
    __syncthreads();

    // Z0[b,i] = sum_j M[i,j] * x[b,j]
    float z0 = 0.f;
    const float* xb = sx + b*D;
#pragma unroll 8
    for (int j = 0; j < D; ++j)
        z0 = fmaf(sT[j*97 + i], xb[j], z0);

    // LayerNorm over i within each b (3 warps per b)
    float s1 = z0, s2 = z0*z0;
#pragma unroll
    for (int o = 16; o; o >>= 1) {
        s1 += __shfl_xor_sync(0xffffffffu, s1, o);
        s2 += __shfl_xor_sync(0xffffffffu, s2, o);
    }
    const int w = tid >> 5, lane = tid & 31;
    if (lane == 0) { sR[w][0] = s1; sR[w][1] = s2; }
    __syncthreads();
    const float mu  = (sR[3*b][0]+sR[3*b+1][0]+sR[3*b+2][0]) * (1.f/D);
    const float ex2 = (sR[3*b][1]+sR[3*b+1][1]+sR[3*b+2][1]) * (1.f/D);
    const float rstd = rsqrtf(ex2 - mu*mu + LN_EPS);
    const float z = (z0 - mu)*rstd*gamma[i] + beta[i];
    sZ[tid] = z;
    __syncthreads();                   // all phase-1 reads of sT/sx done

    // overwrite sT with W^T: sT[j*97+i] = W[s, i*96+j]
#pragma unroll
    for (int r = 0; r < 12; ++r) {
        const int f = tid + r*768;
        sT[(f % D)*97 + f / D] = wreg[r];
    }
    __syncthreads();

    // T[b,i] = sum_j Z[b,j] * W[s,i,j];  A = T + Z0
    float acc = 0.f;
    const float* zb = sZ + b*D;
#pragma unroll 8
    for (int j = 0; j < D; ++j)
        acc = fmaf(zb[j], sT[j*97 + i], acc);

    g_A[(size_t)s*ND + tid] = acc + z0;
}

// ---------------- K4: split-K GEMM  part[z][t,n] = sum_{s in chunk} L[s,t]*A[s,n]
#define BT 64
#define BN 64
#define BK 16
#define KSPLIT 4
#define KCH (S/KSPLIT)     // 256
__global__ __launch_bounds__(256) void k4_gemm(const float* __restrict__ L)
{
    __shared__ float Ls[BK][BT];
    __shared__ float As[BK][BN];
    const int tid = threadIdx.x;
    const int n0  = blockIdx.x * BN;
    const int t0  = blockIdx.y * BT;
    const int z   = blockIdx.z;
    const int tx  = tid & 15;          // n micro
    const int ty  = tid >> 4;          // t micro
    float acc[4][4] = {};

    const int kbeg = z * KCH;
    for (int ks = kbeg; ks < kbeg + KCH; ks += BK) {
#pragma unroll
        for (int r = 0; r < 4; ++r) {
            const int f  = tid + r*256;
            const int kk = f >> 6, c = f & 63;
            Ls[kk][c] = L  [(size_t)(ks+kk)*S  + t0 + c];
            As[kk][c] = g_A[(size_t)(ks+kk)*ND + n0 + c];
        }
        __syncthreads();
#pragma unroll
        for (int kk = 0; kk < BK; ++kk) {
            const float4 lv = *reinterpret_cast<const float4*>(&Ls[kk][ty*4]);
            const float4 av = *reinterpret_cast<const float4*>(&As[kk][tx*4]);
            const float l[4] = {lv.x, lv.y, lv.z, lv.w};
            const float a[4] = {av.x, av.y, av.z, av.w};
#pragma unroll
            for (int u = 0; u < 4; ++u)
#pragma unroll
                for (int v = 0; v < 4; ++v)
                    acc[u][v] = fmaf(l[u], a[v], acc[u][v]);
        }
        __syncthreads();
    }

    float* base = g_part + (size_t)z*(S*ND);
#pragma unroll
    for (int u = 0; u < 4; ++u) {
        const int t = t0 + ty*4 + u;
        float4 v4 = make_float4(acc[u][0], acc[u][1], acc[u][2], acc[u][3]);
        *reinterpret_cast<float4*>(base + (size_t)t*ND + n0 + tx*4) = v4;
    }
}

// ---------------- K5: reduce 4 partials, remap (t,n) -> out[b,t,i] ---------
__global__ __launch_bounds__(256) void k5_reduce(float* __restrict__ out)
{
    const int e  = blockIdx.x*blockDim.x + threadIdx.x;  // float4 index, 0..196607
    const int n4 = e % (ND/4);
    const int t  = e / (ND/4);
    const int n  = n4 * 4;
    const int b  = n / D, i = n % D;

    const float4* p = reinterpret_cast<const float4*>(g_part) + e;
    float4 a = p[0];
    const size_t step = (size_t)(S*ND)/4;
#pragma unroll
    for (int z = 1; z < KSPLIT; ++z) {
        float4 q = p[z*step];
        a.x += q.x; a.y += q.y; a.z += q.z; a.w += q.w;
    }
    *reinterpret_cast<float4*>(out + (size_t)b*(S*D) + (size_t)t*D + i) = a;
}

// ---------------- launch ----------------------------------------------------
extern "C" void kernel_launch(void* const* d_in, const int* in_sizes, int n_in,
                              void* d_out, int out_size)
{
    const float* x     = (const float*)d_in[0];   // (8,1024,96)
    const float* M     = (const float*)d_in[1];   // (96,96)
    const float* P     = (const float*)d_in[2];   // (96,96,8)
    const float* L     = (const float*)d_in[3];   // (1024,1024)
    const float* gamma = (const float*)d_in[4];   // (96)
    const float* beta  = (const float*)d_in[5];   // (96)
    float* out = (float*)d_out;                   // (8,1024,96)

    k2_basis <<<(MTOT*(S/SCHUNK))/256, 256>>>(P);            // 576 blocks
    k13_fused<<<S, 768>>>(x, M, gamma, beta);                // 1024 blocks
    k4_gemm  <<<dim3(ND/BN, S/BT, KSPLIT), 256>>>(L);        // 768 blocks
    k5_reduce<<<(S*ND/4)/256, 256>>>(out);                   // 768 blocks
}

// round 3
// speedup vs baseline: 1.7211x; 1.0361x over previous
#include <cuda_runtime.h>
#include <cstdint>

#define B    8
#define S    1024
#define D    96
#define G    8
#define MTOT (D*D)          // 9216
#define ND   (B*D)          // 768
#define DPAD 100            // padded smem row (100 floats = 400B, conflict-free f4)
#define LN_EPS 1e-5f
#define TWO_PI 6.283185307179586f

// ---------------- scratch (device globals; no allocation allowed) ----------
__device__ float g_W   [S*MTOT];       // W[s, i*96+j]                 (36 MB)
__device__ float g_A   [S*ND];         // (T+Z0) as A[s, b*96+i]       (3 MB)
__device__ float g_part[4*S*ND];       // split-K partials             (12.6 MB)

// ---------------- K2: W[s,m] = sum_g P[m*8+g] * cos(2*pi*s/(8m+g+2)) -------
#define SCHUNK 64
__global__ void k2_basis(const float* __restrict__ P)
{
    const int gidx  = blockIdx.x*blockDim.x + threadIdx.x;
    const int m     = gidx % MTOT;
    const int chunk = gidx / MTOT;
    const int s0    = chunk * SCHUNK;

    float kg[G], c0[G], c1[G], Pv[G];
#pragma unroll
    for (int g = 0; g < G; ++g) {
        const int p    = m*G + g + 2;
        const float fp = (float)p;
        kg[g] = 2.f * cosf(TWO_PI / fp);
        const int r0  = s0 % p;
        const int rm1 = (s0 + p - 1) % p;
        c1[g] = cosf(TWO_PI * (float)r0  / fp);
        c0[g] = cosf(TWO_PI * (float)rm1 / fp);
        Pv[g] = P[m*G + g];
    }

    float* Wp = g_W + (size_t)s0*MTOT + m;
    for (int s = 0; s < SCHUNK; ++s) {
        float w = 0.f;
#pragma unroll
        for (int g = 0; g < G; ++g) w = fmaf(Pv[g], c1[g], w);
        Wp[(size_t)s*MTOT] = w;
#pragma unroll
        for (int g = 0; g < G; ++g) {
            const float cn = fmaf(kg[g], c1[g], -c0[g]);
            c0[g] = c1[g];
            c1[g] = cn;
        }
    }
}

// ---------------- K13: fused project + LN + per-s mixing + residual --------
// one block per s, 768 threads = (b,i). padded row-major smem, float4 LDS.
__global__ __launch_bounds__(768) void k13_fused(const float* __restrict__ x,
                                                 const float* __restrict__ M,
                                                 const float* __restrict__ gamma,
                                                 const float* __restrict__ beta)
{
    const int s   = blockIdx.x;
    const int tid = threadIdx.x;       // b*96 + i
    const int b   = tid / D;
    const int i   = tid % D;

    __shared__ __align__(16) float sBuf[D*DPAD];   // M rows, then W rows (padded)
    __shared__ __align__(16) float sx  [ND];
    __shared__ __align__(16) float sZ  [ND];
    __shared__ float sR[24][2];

    // prefetch W row-chunk (LDGs fly during phase 1)
    float wreg[12];
    const float* Ws = g_W + (size_t)s*MTOT;
#pragma unroll
    for (int r = 0; r < 12; ++r) wreg[r] = Ws[tid + r*768];

    sx[tid] = x[((size_t)b*S + s)*D + i];

    // stage M row-major into padded rows: sBuf[row*100 + col]
#pragma unroll
    for (int r = 0; r < 12; ++r) {
        const int f = tid + r*768;
        sBuf[(f / D)*DPAD + (f % D)] = M[f];
    }
    __syncthreads();

    // Z0[b,i] = dot(M[i,:], x[b,:])  (float4 smem reads, conflict-free)
    float z0 = 0.f;
    {
        const float4* mr = reinterpret_cast<const float4*>(sBuf + i*DPAD);
        const float4* xr = reinterpret_cast<const float4*>(sx + b*D);
#pragma unroll
        for (int j4 = 0; j4 < D/4; ++j4) {
            const float4 m4 = mr[j4];
            const float4 x4 = xr[j4];
            z0 = fmaf(m4.x, x4.x, z0);
            z0 = fmaf(m4.y, x4.y, z0);
            z0 = fmaf(m4.z, x4.z, z0);
            z0 = fmaf(m4.w, x4.w, z0);
        }
    }

    // LayerNorm over i within each b (each warp lies in a single b: 96 = 3*32)
    float s1 = z0, s2 = z0*z0;
#pragma unroll
    for (int o = 16; o; o >>= 1) {
        s1 += __shfl_xor_sync(0xffffffffu, s1, o);
        s2 += __shfl_xor_sync(0xffffffffu, s2, o);
    }
    const int w = tid >> 5, lane = tid & 31;
    if (lane == 0) { sR[w][0] = s1; sR[w][1] = s2; }
    __syncthreads();                   // also: all phase-1 sBuf reads complete
    const float mu  = (sR[3*b][0]+sR[3*b+1][0]+sR[3*b+2][0]) * (1.f/D);
    const float ex2 = (sR[3*b][1]+sR[3*b+1][1]+sR[3*b+2][1]) * (1.f/D);
    const float rstd = rsqrtf(ex2 - mu*mu + LN_EPS);
    sZ[tid] = (z0 - mu)*rstd*gamma[i] + beta[i];

    // overwrite sBuf with W rows (row-major, padded)
#pragma unroll
    for (int r = 0; r < 12; ++r) {
        const int f = tid + r*768;
        sBuf[(f / D)*DPAD + (f % D)] = wreg[r];
    }
    __syncthreads();

    // T[b,i] = dot(W[s,i,:], Z[b,:]);  A = T + Z0
    float acc = 0.f;
    {
        const float4* wr = reinterpret_cast<const float4*>(sBuf + i*DPAD);
        const float4* zr = reinterpret_cast<const float4*>(sZ + b*D);
#pragma unroll
        for (int j4 = 0; j4 < D/4; ++j4) {
            const float4 w4 = wr[j4];
            const float4 z4 = zr[j4];
            acc = fmaf(w4.x, z4.x, acc);
            acc = fmaf(w4.y, z4.y, acc);
            acc = fmaf(w4.z, z4.z, acc);
            acc = fmaf(w4.w, z4.w, acc);
        }
    }
    g_A[(size_t)s*ND + tid] = acc + z0;
}

// ---------------- K4: split-K GEMM, 128x64 tile, 8x4 micro, double-buffered
#define BT 128
#define BN 64
#define BK 16
#define KSPLIT 4
#define KCH (S/KSPLIT)     // 256
#define NIT (KCH/BK)       // 16
__global__ __launch_bounds__(256) void k4_gemm(const float* __restrict__ L)
{
    __shared__ __align__(16) float Ls[2][BK][BT];   // 2 * 8 KB
    __shared__ __align__(16) float As[2][BK][BN];   // 2 * 4 KB
    const int tid = threadIdx.x;
    const int n0  = blockIdx.x * BN;
    const int t0  = blockIdx.y * BT;
    const int z   = blockIdx.z;
    const int tx  = tid & 15;          // n micro (4 cols)
    const int ty  = tid >> 4;          // t micro (8 rows)
    const int kbeg = z * KCH;

    // load indices
    const int lkk0 = tid >> 5,        lc0 = (tid & 31) * 4;        // Ls part 0
    const int lkk1 = (tid+256) >> 5,  lc1 = lc0;                    // Ls part 1
    const int akk  = tid >> 4,        ac  = (tid & 15) * 4;        // As

    float acc[8][4] = {};
    float4 pL0, pL1, pA;

    // prime buffer 0
    pL0 = *reinterpret_cast<const float4*>(&L[(size_t)(kbeg+lkk0)*S + t0 + lc0]);
    pL1 = *reinterpret_cast<const float4*>(&L[(size_t)(kbeg+lkk1)*S + t0 + lc1]);
    pA  = *reinterpret_cast<const float4*>(&g_A[(size_t)(kbeg+akk)*ND + n0 + ac]);
    *reinterpret_cast<float4*>(&Ls[0][lkk0][lc0]) = pL0;
    *reinterpret_cast<float4*>(&Ls[0][lkk1][lc1]) = pL1;
    *reinterpret_cast<float4*>(&As[0][akk][ac])   = pA;
    __syncthreads();

    for (int it = 0; it < NIT; ++it) {
        const int cur = it & 1;
        if (it + 1 < NIT) {
            const int ks = kbeg + (it+1)*BK;
            pL0 = *reinterpret_cast<const float4*>(&L[(size_t)(ks+lkk0)*S + t0 + lc0]);
            pL1 = *reinterpret_cast<const float4*>(&L[(size_t)(ks+lkk1)*S + t0 + lc1]);
            pA  = *reinterpret_cast<const float4*>(&g_A[(size_t)(ks+akk)*ND + n0 + ac]);
        }
#pragma unroll
        for (int kk = 0; kk < BK; ++kk) {
            const float4 l0 = *reinterpret_cast<const float4*>(&Ls[cur][kk][ty*8]);
            const float4 l1 = *reinterpret_cast<const float4*>(&Ls[cur][kk][ty*8+4]);
            const float4 a4 = *reinterpret_cast<const float4*>(&As[cur][kk][tx*4]);
            const float lv[8] = {l0.x,l0.y,l0.z,l0.w,l1.x,l1.y,l1.z,l1.w};
            const float av[4] = {a4.x,a4.y,a4.z,a4.w};
#pragma unroll
            for (int u = 0; u < 8; ++u)
#pragma unroll
                for (int v = 0; v < 4; ++v)
                    acc[u][v] = fmaf(lv[u], av[v], acc[u][v]);
        }
        if (it + 1 < NIT) {
            const int nxt = cur ^ 1;
            *reinterpret_cast<float4*>(&Ls[nxt][lkk0][lc0]) = pL0;
            *reinterpret_cast<float4*>(&Ls[nxt][lkk1][lc1]) = pL1;
            *reinterpret_cast<float4*>(&As[nxt][akk][ac])   = pA;
        }
        __syncthreads();
    }

    float* base = g_part + (size_t)z*(S*ND);
#pragma unroll
    for (int u = 0; u < 8; ++u) {
        const int t = t0 + ty*8 + u;
        float4 v4 = make_float4(acc[u][0], acc[u][1], acc[u][2], acc[u][3]);
        *reinterpret_cast<float4*>(base + (size_t)t*ND + n0 + tx*4) = v4;
    }
}

// ---------------- K5: reduce 4 partials, remap (t,n) -> out[b,t,i] ---------
// 2 float4s per thread for MLP
__global__ __launch_bounds__(256) void k5_reduce(float* __restrict__ out)
{
    const int base_e = (blockIdx.x*blockDim.x + threadIdx.x) * 2;
    const size_t step = (size_t)(S*ND)/4;
#pragma unroll
    for (int q = 0; q < 2; ++q) {
        const int e  = base_e + q;
        const int n4 = e % (ND/4);
        const int t  = e / (ND/4);
        const int n  = n4 * 4;
        const int b  = n / D, i = n % D;
        const float4* p = reinterpret_cast<const float4*>(g_part) + e;
        float4 a = p[0];
#pragma unroll
        for (int zz = 1; zz < KSPLIT; ++zz) {
            float4 qv = p[zz*step];
            a.x += qv.x; a.y += qv.y; a.z += qv.z; a.w += qv.w;
        }
        *reinterpret_cast<float4*>(out + (size_t)b*(S*D) + (size_t)t*D + i) = a;
    }
}

// ---------------- launch ----------------------------------------------------
extern "C" void kernel_launch(void* const* d_in, const int* in_sizes, int n_in,
                              void* d_out, int out_size)
{
    const float* x     = (const float*)d_in[0];   // (8,1024,96)
    const float* M     = (const float*)d_in[1];   // (96,96)
    const float* P     = (const float*)d_in[2];   // (96,96,8)
    const float* L     = (const float*)d_in[3];   // (1024,1024)
    const float* gamma = (const float*)d_in[4];   // (96)
    const float* beta  = (const float*)d_in[5];   // (96)
    float* out = (float*)d_out;                   // (8,1024,96)

    k2_basis <<<(MTOT*(S/SCHUNK))/256, 256>>>(P);            // 576 blocks
    k13_fused<<<S, 768>>>(x, M, gamma, beta);                // 1024 blocks
    k4_gemm  <<<dim3(ND/BN, S/BT, KSPLIT), 256>>>(L);        // 384 blocks
    k5_reduce<<<(S*ND/8)/256, 256>>>(out);                   // 384 blocks
}

// round 4
// speedup vs baseline: 1.8746x; 1.0892x over previous
#include <cuda_runtime.h>
#include <cuda_bf16.h>
#include <cstdint>

#define B    8
#define S    1024
#define D    96
#define G    8
#define MTOT (D*D)          // 9216
#define ND   (B*D)          // 768
#define DPAD 100
#define LN_EPS 1e-5f
#define TWO_PI 6.283185307179586f

// ---------------- scratch (device globals; no allocation allowed) ----------
__device__ __nv_bfloat16 g_W[S*MTOT];  // W[s, i*96+j] in bf16         (18 MB)
__device__ float g_A   [S*ND];         // (T+Z0) as A[s, b*96+i]       (3 MB)
__device__ float g_part[4*S*ND];       // split-K partials             (12.6 MB)

// ---------------- packed f32x2 helpers (sm_103a) ---------------------------
__device__ __forceinline__ unsigned long long splat2(float a) {
    unsigned long long r;
    asm("mov.b64 %0, {%1, %1};" : "=l"(r) : "f"(a));
    return r;
}
__device__ __forceinline__ void fma2(unsigned long long& d,
                                     unsigned long long a,
                                     unsigned long long b) {
    asm("fma.rn.f32x2 %0, %1, %2, %0;" : "+l"(d) : "l"(a), "l"(b));
}
__device__ __forceinline__ float2 unpack2(unsigned long long v) {
    float lo, hi;
    asm("mov.b64 {%0, %1}, %2;" : "=f"(lo), "=f"(hi) : "l"(v));
    return make_float2(lo, hi);
}

// ---------------- K2: W[s,m] = sum_g P[m*8+g] * cos(2*pi*s/(8m+g+2)) -------
#define SCHUNK 64
__global__ void k2_basis(const float* __restrict__ P)
{
    const int gidx  = blockIdx.x*blockDim.x + threadIdx.x;
    const int m     = gidx % MTOT;
    const int chunk = gidx / MTOT;
    const int s0    = chunk * SCHUNK;

    float kg[G], c0[G], c1[G], Pv[G];
#pragma unroll
    for (int g = 0; g < G; ++g) {
        const int p    = m*G + g + 2;
        const float fp = (float)p;
        kg[g] = 2.f * cosf(TWO_PI / fp);
        const int r0  = s0 % p;
        const int rm1 = (s0 + p - 1) % p;
        c1[g] = cosf(TWO_PI * (float)r0  / fp);
        c0[g] = cosf(TWO_PI * (float)rm1 / fp);
        Pv[g] = P[m*G + g];
    }

    __nv_bfloat16* Wp = g_W + (size_t)s0*MTOT + m;
    for (int s = 0; s < SCHUNK; ++s) {
        float w = 0.f;
#pragma unroll
        for (int g = 0; g < G; ++g) w = fmaf(Pv[g], c1[g], w);
        Wp[(size_t)s*MTOT] = __float2bfloat16(w);
#pragma unroll
        for (int g = 0; g < G; ++g) {
            const float cn = fmaf(kg[g], c1[g], -c0[g]);
            c0[g] = c1[g];
            c1[g] = cn;
        }
    }
}

// ---------------- K13: fused project + LN + per-s mixing + residual --------
__global__ __launch_bounds__(768) void k13_fused(const float* __restrict__ x,
                                                 const float* __restrict__ M,
                                                 const float* __restrict__ gamma,
                                                 const float* __restrict__ beta)
{
    const int s   = blockIdx.x;
    const int tid = threadIdx.x;       // b*96 + i
    const int b   = tid / D;
    const int i   = tid % D;

    __shared__ __align__(16) float sBuf[D*DPAD];   // M rows, then W rows
    __shared__ __align__(16) float sx  [ND];
    __shared__ __align__(16) float sZ  [ND];
    __shared__ float sR[24][2];

    // prefetch W row-chunk as bf16 pairs (LDGs fly during phase 1)
    __nv_bfloat162 wreg[6];
    const __nv_bfloat162* Wp =
        reinterpret_cast<const __nv_bfloat162*>(g_W + (size_t)s*MTOT);
#pragma unroll
    for (int r = 0; r < 6; ++r) wreg[r] = Wp[tid + r*768];

    sx[tid] = x[((size_t)b*S + s)*D + i];

#pragma unroll
    for (int r = 0; r < 12; ++r) {
        const int f = tid + r*768;
        sBuf[(f / D)*DPAD + (f % D)] = M[f];
    }
    __syncthreads();

    // Z0[b,i] = dot(M[i,:], x[b,:])
    float z0 = 0.f;
    {
        const float4* mr = reinterpret_cast<const float4*>(sBuf + i*DPAD);
        const float4* xr = reinterpret_cast<const float4*>(sx + b*D);
#pragma unroll
        for (int j4 = 0; j4 < D/4; ++j4) {
            const float4 m4 = mr[j4];
            const float4 x4 = xr[j4];
            z0 = fmaf(m4.x, x4.x, z0);
            z0 = fmaf(m4.y, x4.y, z0);
            z0 = fmaf(m4.z, x4.z, z0);
            z0 = fmaf(m4.w, x4.w, z0);
        }
    }

    // LayerNorm over i within each b
    float s1 = z0, s2 = z0*z0;
#pragma unroll
    for (int o = 16; o; o >>= 1) {
        s1 += __shfl_xor_sync(0xffffffffu, s1, o);
        s2 += __shfl_xor_sync(0xffffffffu, s2, o);
    }
    const int w = tid >> 5, lane = tid & 31;
    if (lane == 0) { sR[w][0] = s1; sR[w][1] = s2; }
    __syncthreads();
    const float mu  = (sR[3*b][0]+sR[3*b+1][0]+sR[3*b+2][0]) * (1.f/D);
    const float ex2 = (sR[3*b][1]+sR[3*b+1][1]+sR[3*b+2][1]) * (1.f/D);
    const float rstd = rsqrtf(ex2 - mu*mu + LN_EPS);
    sZ[tid] = (z0 - mu)*rstd*gamma[i] + beta[i];

    // overwrite sBuf with W rows (bf16 -> f32, padded row-major)
#pragma unroll
    for (int r = 0; r < 6; ++r) {
        const int e0  = 2*(tid + r*768);
        const int row = e0 / D, col = e0 % D;
        const float2 v = __bfloat1622float2(wreg[r]);
        sBuf[row*DPAD + col]     = v.x;
        sBuf[row*DPAD + col + 1] = v.y;
    }
    __syncthreads();

    // T[b,i] = dot(W[s,i,:], Z[b,:]);  A = T + Z0
    float acc = 0.f;
    {
        const float4* wr = reinterpret_cast<const float4*>(sBuf + i*DPAD);
        const float4* zr = reinterpret_cast<const float4*>(sZ + b*D);
#pragma unroll
        for (int j4 = 0; j4 < D/4; ++j4) {
            const float4 w4 = wr[j4];
            const float4 z4 = zr[j4];
            acc = fmaf(w4.x, z4.x, acc);
            acc = fmaf(w4.y, z4.y, acc);
            acc = fmaf(w4.z, z4.z, acc);
            acc = fmaf(w4.w, z4.w, acc);
        }
    }
    g_A[(size_t)s*ND + tid] = acc + z0;
}

// ---------------- K4: split-K GEMM, 128x64 tile, 8x4 micro, f32x2 FMA ------
#define BT 128
#define BN 64
#define BK 16
#define KSPLIT 4
#define KCH (S/KSPLIT)     // 256
#define NIT (KCH/BK)       // 16
__global__ __launch_bounds__(256) void k4_gemm(const float* __restrict__ L)
{
    __shared__ __align__(16) float Ls[2][BK][BT];
    __shared__ __align__(16) float As[2][BK][BN];
    const int tid = threadIdx.x;
    const int n0  = blockIdx.x * BN;
    const int t0  = blockIdx.y * BT;
    const int z   = blockIdx.z;
    const int tx  = tid & 15;          // n micro (4 cols)
    const int ty  = tid >> 4;          // t micro (8 rows = 4 packed pairs)
    const int kbeg = z * KCH;

    const int lkk0 = tid >> 5,       lc0 = (tid & 31) * 4;
    const int lkk1 = (tid+256) >> 5, lc1 = lc0;
    const int akk  = tid >> 4,       ac  = (tid & 15) * 4;

    unsigned long long acc2[4][4];     // [t-pair][n], packed along t
#pragma unroll
    for (int u = 0; u < 4; ++u)
#pragma unroll
        for (int v = 0; v < 4; ++v) acc2[u][v] = 0ull;

    float4 pL0, pL1, pA;
    pL0 = *reinterpret_cast<const float4*>(&L[(size_t)(kbeg+lkk0)*S + t0 + lc0]);
    pL1 = *reinterpret_cast<const float4*>(&L[(size_t)(kbeg+lkk1)*S + t0 + lc1]);
    pA  = *reinterpret_cast<const float4*>(&g_A[(size_t)(kbeg+akk)*ND + n0 + ac]);
    *reinterpret_cast<float4*>(&Ls[0][lkk0][lc0]) = pL0;
    *reinterpret_cast<float4*>(&Ls[0][lkk1][lc1]) = pL1;
    *reinterpret_cast<float4*>(&As[0][akk][ac])   = pA;
    __syncthreads();

    for (int it = 0; it < NIT; ++it) {
        const int cur = it & 1;
        if (it + 1 < NIT) {
            const int ks = kbeg + (it+1)*BK;
            pL0 = *reinterpret_cast<const float4*>(&L[(size_t)(ks+lkk0)*S + t0 + lc0]);
            pL1 = *reinterpret_cast<const float4*>(&L[(size_t)(ks+lkk1)*S + t0 + lc1]);
            pA  = *reinterpret_cast<const float4*>(&g_A[(size_t)(ks+akk)*ND + n0 + ac]);
        }
#pragma unroll
        for (int kk = 0; kk < BK; ++kk) {
            // natively-packed t-pairs (8 consecutive t values = 4 x f32x2)
            const ulonglong2 lp0 =
                *reinterpret_cast<const ulonglong2*>(&Ls[cur][kk][ty*8]);
            const ulonglong2 lp1 =
                *reinterpret_cast<const ulonglong2*>(&Ls[cur][kk][ty*8+4]);
            const unsigned long long lp[4] = {lp0.x, lp0.y, lp1.x, lp1.y};
            const float4 a4 = *reinterpret_cast<const float4*>(&As[cur][kk][tx*4]);
            const unsigned long long ap[4] =
                {splat2(a4.x), splat2(a4.y), splat2(a4.z), splat2(a4.w)};
#pragma unroll
            for (int u = 0; u < 4; ++u)
#pragma unroll
                for (int v = 0; v < 4; ++v)
                    fma2(acc2[u][v], lp[u], ap[v]);
        }
        if (it + 1 < NIT) {
            const int nxt = cur ^ 1;
            *reinterpret_cast<float4*>(&Ls[nxt][lkk0][lc0]) = pL0;
            *reinterpret_cast<float4*>(&Ls[nxt][lkk1][lc1]) = pL1;
            *reinterpret_cast<float4*>(&As[nxt][akk][ac])   = pA;
        }
        __syncthreads();
    }

    float* base = g_part + (size_t)z*(S*ND);
#pragma unroll
    for (int u = 0; u < 4; ++u) {
        float2 r0 = unpack2(acc2[u][0]);
        float2 r1 = unpack2(acc2[u][1]);
        float2 r2 = unpack2(acc2[u][2]);
        float2 r3 = unpack2(acc2[u][3]);
        const int t = t0 + ty*8 + 2*u;
        *reinterpret_cast<float4*>(base + (size_t)t*ND + n0 + tx*4) =
            make_float4(r0.x, r1.x, r2.x, r3.x);
        *reinterpret_cast<float4*>(base + (size_t)(t+1)*ND + n0 + tx*4) =
            make_float4(r0.y, r1.y, r2.y, r3.y);
    }
}

// ---------------- K5: reduce 4 partials, remap (t,n) -> out[b,t,i] ---------
__global__ __launch_bounds__(256) void k5_reduce(float* __restrict__ out)
{
    const int base_e = (blockIdx.x*blockDim.x + threadIdx.x) * 2;
    const size_t step = (size_t)(S*ND)/4;
#pragma unroll
    for (int q = 0; q < 2; ++q) {
        const int e  = base_e + q;
        const int n4 = e % (ND/4);
        const int t  = e / (ND/4);
        const int n  = n4 * 4;
        const int b  = n / D, i = n % D;
        const float4* p = reinterpret_cast<const float4*>(g_part) + e;
        float4 a = p[0];
#pragma unroll
        for (int zz = 1; zz < KSPLIT; ++zz) {
            float4 qv = p[zz*step];
            a.x += qv.x; a.y += qv.y; a.z += qv.z; a.w += qv.w;
        }
        *reinterpret_cast<float4*>(out + (size_t)b*(S*D) + (size_t)t*D + i) = a;
    }
}

// ---------------- launch ----------------------------------------------------
extern "C" void kernel_launch(void* const* d_in, const int* in_sizes, int n_in,
                              void* d_out, int out_size)
{
    const float* x     = (const float*)d_in[0];   // (8,1024,96)
    const float* M     = (const float*)d_in[1];   // (96,96)
    const float* P     = (const float*)d_in[2];   // (96,96,8)
    const float* L     = (const float*)d_in[3];   // (1024,1024)
    const float* gamma = (const float*)d_in[4];   // (96)
    const float* beta  = (const float*)d_in[5];   // (96)
    float* out = (float*)d_out;                   // (8,1024,96)

    k2_basis <<<(MTOT*(S/SCHUNK))/256, 256>>>(P);            // 576 blocks
    k13_fused<<<S, 768>>>(x, M, gamma, beta);                // 1024 blocks
    k4_gemm  <<<dim3(ND/BN, S/BT, KSPLIT), 256>>>(L);        // 384 blocks
    k5_reduce<<<(S*ND/8)/256, 256>>>(out);                   // 384 blocks
}